// round 3
// baseline (speedup 1.0000x reference)
#include <cuda_runtime.h>
#include <math.h>

#define NN  5
#define BB  8
#define CC  256
#define HWD 1024
#define KB  16
#define TO  64
#define TP  64

#define FMA2(d, a, b) \
    asm("fma.rn.f32x2 %0, %1, %2, %3;" : "=l"(d) : "l"(a), "l"(b), "l"(d))
#define PACK2(d, lo, hi) \
    asm("mov.b64 %0, {%1, %2};" : "=l"(d) : "r"(__float_as_uint(lo)), "r"(__float_as_uint(hi)))
#define UNPACK2(lo, hi, s) do { unsigned int _u0, _u1; \
    asm("mov.b64 {%0, %1}, %2;" : "=r"(_u0), "=r"(_u1) : "l"(s)); \
    lo = __uint_as_float(_u0); hi = __uint_as_float(_u1); } while (0)

// Preprocessed weights, k-major: [i][c][o].  M = W1+W2, W2 separate.
__device__ float g_Mt [NN * CC * CC];
__device__ float g_W2t[NN * CC * CC];

__global__ void prep_kernel(const float* __restrict__ w) {
    int idx = blockIdx.x * blockDim.x + threadIdx.x;   // (i*CC + c)*CC + o
    if (idx >= NN * CC * CC) return;
    int o = idx & 255;
    int c = (idx >> 8) & 255;
    int i = idx >> 16;
    const float* row = w + (size_t)(i * CC + o) * (2 * CC);
    float w2 = row[CC + c];
    g_W2t[idx] = w2;
    g_Mt[idx]  = row[c] + w2;
}

struct Smem {
    float Xs[2][NN][KB][TP];   // 40 KB  (double-buffered B tiles)
    float Ms[2][KB][TO];       //  8 KB  (k-major A tile, M)
    float Ws[2][KB][TO];       //  8 KB  (k-major A tile, W2)
};

__global__ __launch_bounds__(512, 1) void fused_kernel(
    const float* __restrict__ x,
    const float* __restrict__ bias,
    float* __restrict__ out)
{
    extern __shared__ __align__(16) char smem_raw[];
    Smem& sm = *reinterpret_cast<Smem*>(smem_raw);

    const int i   = blockIdx.z;
    const int o0  = blockIdx.y * TO;
    const int b   = blockIdx.x >> 4;
    const int hw0 = (blockIdx.x & 15) * TP;

    const int tid  = threadIdx.x;
    const int lane = tid & 31;
    const int warp = tid >> 5;
    const int tx = ((warp & 1) << 3) | (lane & 7);    // 0..15: pixel group of 4
    const int ty = ((warp >> 1) << 2) | (lane >> 3);  // 0..31: 2 o-rows each

    unsigned long long accV[NN][2][2];
    unsigned long long accU[2][2];
    #pragma unroll
    for (int j = 0; j < NN; j++)
        #pragma unroll
        for (int r = 0; r < 2; r++) { accV[j][r][0] = 0ULL; accV[j][r][1] = 0ULL; }
    #pragma unroll
    for (int r = 0; r < 2; r++) { accU[r][0] = 0ULL; accU[r][1] = 0ULL; }

    // ---- async load of one K-chunk into buffer bb ----
    auto issue_chunk = [&](int k0, int bb) {
        // B tiles: 5*16*16 = 1280 float4 over 512 threads
        #pragma unroll
        for (int t = 0; t < 3; t++) {
            int idx = tid + t * 512;
            if (idx < 1280) {
                int p4 = idx & 15;
                int k  = (idx >> 4) & 15;
                int j  = idx >> 8;
                const float* src = x + ((((size_t)j * BB + b) * CC + k0 + k) * HWD)
                                     + hw0 + p4 * 4;
                unsigned dst = (unsigned)__cvta_generic_to_shared(&sm.Xs[bb][j][k][p4 * 4]);
                asm volatile("cp.async.cg.shared.global [%0], [%1], 16;"
                             :: "r"(dst), "l"(src));
            }
        }
        // A tiles: 2*16*16 = 512 float4, one per thread (k-major, no transpose needed)
        {
            int tsel = tid >> 8;
            int k    = (tid >> 4) & 15;
            int p4   = tid & 15;
            const float* base = tsel ? g_W2t : g_Mt;
            const float* src  = base + (size_t)(i * CC + k0 + k) * CC + o0 + p4 * 4;
            float* d = tsel ? &sm.Ws[bb][k][p4 * 4] : &sm.Ms[bb][k][p4 * 4];
            unsigned dst = (unsigned)__cvta_generic_to_shared(d);
            asm volatile("cp.async.cg.shared.global [%0], [%1], 16;"
                         :: "r"(dst), "l"(src));
        }
        asm volatile("cp.async.commit_group;");
    };

    issue_chunk(0, 0);

    for (int c = 0; c < CC / KB; c++) {
        asm volatile("cp.async.wait_group 0;");
        __syncthreads();                       // chunk c visible; prev compute done
        if (c < CC / KB - 1) issue_chunk((c + 1) * KB, (c + 1) & 1);
        const int cur = c & 1;

        #pragma unroll
        for (int k = 0; k < KB; k++) {
            const float2 am = *(const float2*)&sm.Ms[cur][k][ty * 2];
            const float2 aw = *(const float2*)&sm.Ws[cur][k][ty * 2];
            unsigned long long aM2[2], aW2[2];
            PACK2(aM2[0], am.x, am.x); PACK2(aM2[1], am.y, am.y);
            PACK2(aW2[0], aw.x, aw.x); PACK2(aW2[1], aw.y, aw.y);

            unsigned long long b2[NN][2];
            #pragma unroll
            for (int j = 0; j < NN; j++) {
                const ulonglong2 q = *(const ulonglong2*)&sm.Xs[cur][j][k][tx * 4];
                b2[j][0] = q.x; b2[j][1] = q.y;
            }
            const ulonglong2 qu = *(const ulonglong2*)&sm.Xs[cur][i][k][tx * 4];

            #pragma unroll
            for (int j = 0; j < NN; j++)
                #pragma unroll
                for (int r = 0; r < 2; r++) {
                    FMA2(accV[j][r][0], aM2[r], b2[j][0]);
                    FMA2(accV[j][r][1], aM2[r], b2[j][1]);
                }
            FMA2(accU[0][0], aW2[0], qu.x); FMA2(accU[0][1], aW2[0], qu.y);
            FMA2(accU[1][0], aW2[1], qu.x); FMA2(accU[1][1], aW2[1], qu.y);
        }
    }

    // ---- fused epilogue ----
    #pragma unroll
    for (int r = 0; r < 2; r++) {
        const int o  = o0 + ty * 2 + r;
        const float bv = bias[i * CC + o];
        float xr[NN][4];
        #pragma unroll
        for (int j = 0; j < NN; j++) {
            const float4 q = *(const float4*)(
                x + ((((size_t)j * BB + b) * CC + o) * HWD) + hw0 + tx * 4);
            xr[j][0] = q.x; xr[j][1] = q.y; xr[j][2] = q.z; xr[j][3] = q.w;
        }
        float uu[4];
        UNPACK2(uu[0], uu[1], accU[r][0]);
        UNPACK2(uu[2], uu[3], accU[r][1]);
        float vv[NN][4];
        #pragma unroll
        for (int j = 0; j < NN; j++) {
            UNPACK2(vv[j][0], vv[j][1], accV[j][r][0]);
            UNPACK2(vv[j][2], vv[j][3], accV[j][r][1]);
        }
        float resv[4];
        #pragma unroll
        for (int cix = 0; cix < 4; cix++) {
            const float u = uu[cix] + bv;
            float e[NN];
            float m = 0.f;
            #pragma unroll
            for (int j = 0; j < NN; j++) {
                float t = vv[j][cix] + u;
                float d = fabsf(xr[j][cix] - t);
                e[j] = (d > 0.3f) ? d : 0.f;
                m = fmaxf(m, e[j]);
            }
            float s = 0.f, a = 0.f;
            #pragma unroll
            for (int j = 0; j < NN; j++) {
                float wgt = __expf(e[j] - m);
                s += wgt;
                a = fmaf(wgt, xr[j][cix], a);
            }
            resv[cix] = a / s;
        }
        *(float4*)(out + ((((size_t)i * BB + b) * CC + o) * HWD) + hw0 + tx * 4) =
            make_float4(resv[0], resv[1], resv[2], resv[3]);
    }
}

extern "C" void kernel_launch(void* const* d_in, const int* in_sizes, int n_in,
                              void* d_out, int out_size) {
    const float* x    = (const float*)d_in[0];   // [5,8,256,32,32]
    const float* w    = (const float*)d_in[1];   // [5,256,512]
    const float* bias = (const float*)d_in[2];   // [5,256]
    float* out = (float*)d_out;                  // [5,8,256,32,32]

    static int smem_set = 0;
    if (!smem_set) {
        cudaFuncSetAttribute(fused_kernel,
                             cudaFuncAttributeMaxDynamicSharedMemorySize,
                             (int)sizeof(Smem));
        smem_set = 1;
    }

    prep_kernel<<<(NN * CC * CC + 255) / 256, 256>>>(w);
    fused_kernel<<<dim3(128, 4, 5), 512, sizeof(Smem)>>>(x, bias, out);
}

// round 4
// speedup vs baseline: 1.4439x; 1.4439x over previous
#include <cuda_runtime.h>
#include <math.h>

#define NN  5
#define BB  8
#define CC  256
#define HWD 1024
#define KB  16
#define TO  64
#define TP  64
#define NCHUNK (CC / KB)

#define FMA2(d, a, b) \
    asm("fma.rn.f32x2 %0, %1, %2, %3;" : "=l"(d) : "l"(a), "l"(b), "l"(d))
#define UNPACK2(lo, hi, s) do { unsigned int _u0, _u1; \
    asm("mov.b64 {%0, %1}, %2;" : "=r"(_u0), "=r"(_u1) : "l"(s)); \
    lo = __uint_as_float(_u0); hi = __uint_as_float(_u1); } while (0)

// Preprocessed weights, k-major AND pre-duplicated for packed f32x2 FMA:
// g_Md[(i*CC+c)*CC+o] = {m, m} with m = W1[i][o][c] + W2[i][o][c]; g_Wd = {w2, w2}.
__device__ float2 g_Md[NN * CC * CC];
__device__ float2 g_Wd[NN * CC * CC];

__global__ void prep_kernel(const float* __restrict__ w) {
    int idx = blockIdx.x * blockDim.x + threadIdx.x;   // (i*CC + c)*CC + o
    if (idx >= NN * CC * CC) return;
    int o = idx & 255;
    int c = (idx >> 8) & 255;
    int i = idx >> 16;
    const float* row = w + (size_t)(i * CC + o) * (2 * CC);
    float w2 = row[CC + c];
    float m  = row[c] + w2;
    g_Wd[idx] = make_float2(w2, w2);
    g_Md[idx] = make_float2(m, m);
}

struct Smem {
    float  Xs[2][NN][KB][TP];    // 40 KB (double-buffered B tiles)
    float2 Md[2][KB][TO];        // 16 KB (duplicated packed M weights)
    float2 Wd[2][KB][TO];        // 16 KB (duplicated packed W2 weights)
};                               // 72 KB total

__global__ __launch_bounds__(256, 1) void fused_kernel(
    const float* __restrict__ x,
    const float* __restrict__ bias,
    float* __restrict__ out)
{
    extern __shared__ __align__(16) char smem_raw[];
    Smem& sm = *reinterpret_cast<Smem*>(smem_raw);

    const int i   = blockIdx.z;
    const int o0  = blockIdx.y * TO;
    const int b   = blockIdx.x >> 4;
    const int hw0 = (blockIdx.x & 15) * TP;

    const int tid = threadIdx.x;
    const int tx  = tid & 15;                  // pixel group (4 px)
    const int ty  = tid >> 4;                  // o group (4 rows)

    // Packed accumulators: [j][row][pair]
    unsigned long long accV[NN][4][2];
    unsigned long long accU[4][2];
    #pragma unroll
    for (int j = 0; j < NN; j++)
        #pragma unroll
        for (int r = 0; r < 4; r++) { accV[j][r][0] = 0ULL; accV[j][r][1] = 0ULL; }
    #pragma unroll
    for (int r = 0; r < 4; r++) { accU[r][0] = 0ULL; accU[r][1] = 0ULL; }

    // ---- async load of one K-chunk into buffer bb ----
    auto issue_chunk = [&](int k0, int bb) {
        // B tiles: 5*16*16 = 1280 float4 over 256 threads = 5 each
        #pragma unroll
        for (int t = 0; t < 5; t++) {
            int idx = tid + t * 256;
            int p4  = idx & 15;
            int k   = (idx >> 4) & 15;
            int j   = idx >> 8;
            const float* src = x + ((((size_t)j * BB + b) * CC + k0 + k) * HWD)
                                 + hw0 + p4 * 4;
            unsigned dst = (unsigned)__cvta_generic_to_shared(&sm.Xs[bb][j][k][p4 * 4]);
            asm volatile("cp.async.cg.shared.global [%0], [%1], 16;"
                         :: "r"(dst), "l"(src));
        }
        // A tiles (duplicated float2): per array 16k * 32 float4 = 512 float4 -> 2 each
        #pragma unroll
        for (int t = 0; t < 2; t++) {
            int idx = tid + t * 256;
            int k   = idx >> 5;                // 32 float4 per k-row
            int p   = idx & 31;                // float4 index within row (2 float2 each)
            {
                const float4* src = (const float4*)(g_Md + ((size_t)(i * CC + k0 + k)) * CC + o0) + p;
                unsigned dst = (unsigned)__cvta_generic_to_shared(&sm.Md[bb][k][p * 2]);
                asm volatile("cp.async.cg.shared.global [%0], [%1], 16;"
                             :: "r"(dst), "l"(src));
            }
            {
                const float4* src = (const float4*)(g_Wd + ((size_t)(i * CC + k0 + k)) * CC + o0) + p;
                unsigned dst = (unsigned)__cvta_generic_to_shared(&sm.Wd[bb][k][p * 2]);
                asm volatile("cp.async.cg.shared.global [%0], [%1], 16;"
                             :: "r"(dst), "l"(src));
            }
        }
        asm volatile("cp.async.commit_group;");
    };

    issue_chunk(0, 0);

    for (int c = 0; c < NCHUNK; c++) {
        asm volatile("cp.async.wait_group 0;");
        __syncthreads();                       // chunk c visible; prev compute done
        if (c < NCHUNK - 1) issue_chunk((c + 1) * KB, (c + 1) & 1);
        const int cur = c & 1;

        #pragma unroll
        for (int k = 0; k < KB; k++) {
            // A operands: already packed {w,w} pairs in smem
            const ulonglong2 mA = *(const ulonglong2*)&sm.Md[cur][k][ty * 4];
            const ulonglong2 mB = *(const ulonglong2*)&sm.Md[cur][k][ty * 4 + 2];
            const ulonglong2 wA = *(const ulonglong2*)&sm.Wd[cur][k][ty * 4];
            const ulonglong2 wB = *(const ulonglong2*)&sm.Wd[cur][k][ty * 4 + 2];
            const unsigned long long aM2[4] = { mA.x, mA.y, mB.x, mB.y };
            const unsigned long long aW2[4] = { wA.x, wA.y, wB.x, wB.y };

            unsigned long long b2[NN][2];
            #pragma unroll
            for (int j = 0; j < NN; j++) {
                const ulonglong2 q = *(const ulonglong2*)&sm.Xs[cur][j][k][tx * 4];
                b2[j][0] = q.x; b2[j][1] = q.y;
            }
            const ulonglong2 qu = *(const ulonglong2*)&sm.Xs[cur][i][k][tx * 4];

            #pragma unroll
            for (int j = 0; j < NN; j++)
                #pragma unroll
                for (int r = 0; r < 4; r++) {
                    FMA2(accV[j][r][0], aM2[r], b2[j][0]);
                    FMA2(accV[j][r][1], aM2[r], b2[j][1]);
                }
            #pragma unroll
            for (int r = 0; r < 4; r++) {
                FMA2(accU[r][0], aW2[r], qu.x);
                FMA2(accU[r][1], aW2[r], qu.y);
            }
        }
    }

    // ---- fused epilogue: t = v_j + u + b; e = |x_j - t| thresholded; softmax_j; sum ----
    #pragma unroll
    for (int r = 0; r < 4; r++) {
        const int o  = o0 + ty * 4 + r;
        const float bv = bias[i * CC + o];
        float xr[NN][4];
        #pragma unroll
        for (int j = 0; j < NN; j++) {
            const float4 q = *(const float4*)(
                x + ((((size_t)j * BB + b) * CC + o) * HWD) + hw0 + tx * 4);
            xr[j][0] = q.x; xr[j][1] = q.y; xr[j][2] = q.z; xr[j][3] = q.w;
        }
        float uu[4];
        UNPACK2(uu[0], uu[1], accU[r][0]);
        UNPACK2(uu[2], uu[3], accU[r][1]);
        float vv[NN][4];
        #pragma unroll
        for (int j = 0; j < NN; j++) {
            UNPACK2(vv[j][0], vv[j][1], accV[j][r][0]);
            UNPACK2(vv[j][2], vv[j][3], accV[j][r][1]);
        }
        float resv[4];
        #pragma unroll
        for (int cix = 0; cix < 4; cix++) {
            const float u = uu[cix] + bv;
            float e[NN];
            float m = 0.f;                       // all e >= 0, so max >= 0
            #pragma unroll
            for (int j = 0; j < NN; j++) {
                float t = vv[j][cix] + u;
                float d = fabsf(xr[j][cix] - t);
                e[j] = (d > 0.3f) ? d : 0.f;
                m = fmaxf(m, e[j]);
            }
            float s = 0.f, a = 0.f;
            #pragma unroll
            for (int j = 0; j < NN; j++) {
                float wgt = __expf(e[j] - m);
                s += wgt;
                a = fmaf(wgt, xr[j][cix], a);
            }
            resv[cix] = a / s;
        }
        *(float4*)(out + ((((size_t)i * BB + b) * CC + o) * HWD) + hw0 + tx * 4) =
            make_float4(resv[0], resv[1], resv[2], resv[3]);
    }
}

extern "C" void kernel_launch(void* const* d_in, const int* in_sizes, int n_in,
                              void* d_out, int out_size) {
    const float* x    = (const float*)d_in[0];   // [5,8,256,32,32]
    const float* w    = (const float*)d_in[1];   // [5,256,512]
    const float* bias = (const float*)d_in[2];   // [5,256]
    float* out = (float*)d_out;                  // [5,8,256,32,32]

    cudaFuncSetAttribute(fused_kernel,
                         cudaFuncAttributeMaxDynamicSharedMemorySize,
                         (int)sizeof(Smem));

    prep_kernel<<<(NN * CC * CC + 255) / 256, 256>>>(w);
    fused_kernel<<<dim3(128, 4, 5), 256, sizeof(Smem)>>>(x, bias, out);
}